// round 14
// baseline (speedup 1.0000x reference)
#include <cuda_runtime.h>
#include <cuda_bf16.h>
#include <cstdint>

// Problem constants (fixed by the reference)
#define BB 2
#define TT 2048
#define DD 1024
#define HH 16
#define HD 64
#define QKVD 3072   // 3*D
#define MM (BB*TT)  // 4096 rows
#define KDIM 1024   // K of both projections

// ---------------------------------------------------------------------------
// Scratch (no cudaMalloc allowed)
// ---------------------------------------------------------------------------
__device__ __nv_bfloat16 g_xh[(size_t)MM * DD];       // x split
__device__ __nv_bfloat16 g_xl[(size_t)MM * DD];
__device__ __nv_bfloat16 g_wqh[(size_t)QKVD * DD];    // W_qkv split
__device__ __nv_bfloat16 g_wql[(size_t)QKVD * DD];
__device__ __nv_bfloat16 g_woh[(size_t)DD * DD];      // W_out split
__device__ __nv_bfloat16 g_wol[(size_t)DD * DD];
__device__ __nv_bfloat16 g_qkvh[(size_t)MM * QKVD];   // qkv proj, split bf16
__device__ __nv_bfloat16 g_qkvl[(size_t)MM * QKVD];
__device__ __nv_bfloat16 g_ah[(size_t)MM * DD];       // attention out, split
__device__ __nv_bfloat16 g_al[(size_t)MM * DD];

// ---------------------------------------------------------------------------
// Baseline-PTX tensor-core helpers (sm_80-era ISA: compiles for compute_103)
// ---------------------------------------------------------------------------
__device__ __forceinline__ uint32_t smem_to_u32(const void* p) {
    uint32_t a;
    asm("{ .reg .u64 t; cvta.to.shared.u64 t, %1; cvt.u32.u64 %0, t; }"
        : "=r"(a) : "l"(p));
    return a;
}

#define LDSM_X4(r, addr)                                                     \
    asm volatile("ldmatrix.sync.aligned.m8n8.x4.shared.b16 "                 \
        "{%0,%1,%2,%3}, [%4];"                                               \
        : "=r"((r)[0]), "=r"((r)[1]), "=r"((r)[2]), "=r"((r)[3])             \
        : "r"(addr))

#define LDSM_X4_T(r, addr)                                                   \
    asm volatile("ldmatrix.sync.aligned.m8n8.x4.trans.shared.b16 "           \
        "{%0,%1,%2,%3}, [%4];"                                               \
        : "=r"((r)[0]), "=r"((r)[1]), "=r"((r)[2]), "=r"((r)[3])             \
        : "r"(addr))

#define MMA16816(d, a, b)                                                    \
    asm volatile("mma.sync.aligned.m16n8k16.row.col.f32.bf16.bf16.f32 "      \
        "{%0,%1,%2,%3}, {%4,%5,%6,%7}, {%8,%9}, {%0,%1,%2,%3};"              \
        : "+f"((d)[0]), "+f"((d)[1]), "+f"((d)[2]), "+f"((d)[3])             \
        : "r"((a)[0]), "r"((a)[1]), "r"((a)[2]), "r"((a)[3]),                \
          "r"((b)[0]), "r"((b)[1]))

#define CP_ASYNC16(dst, src)                                                 \
    asm volatile("cp.async.cg.shared.global [%0], [%1], 16;"                 \
        :: "r"(dst), "l"(src))
#define CP_COMMIT() asm volatile("cp.async.commit_group;" ::: "memory")
#define CP_WAIT1()  asm volatile("cp.async.wait_group 1;"  ::: "memory")
#define CP_WAIT0()  asm volatile("cp.async.wait_group 0;"  ::: "memory")

__device__ __forceinline__ float ex2f(float x) {
    float r;
    asm("ex2.approx.f32 %0, %1;" : "=f"(r) : "f"(x));
    return r;
}

__device__ __forceinline__ uint32_t pack_bf2(__nv_bfloat16 a, __nv_bfloat16 b) {
    return (uint32_t)__bfloat16_as_ushort(a) |
           ((uint32_t)__bfloat16_as_ushort(b) << 16);
}
// split two fp32 into packed bf16 hi pair + bf16 lo (residual) pair
__device__ __forceinline__ void split2(float f0, float f1,
                                       uint32_t& hi, uint32_t& lo) {
    __nv_bfloat16 h0 = __float2bfloat16(f0);
    __nv_bfloat16 h1 = __float2bfloat16(f1);
    float r0 = f0 - __bfloat162float(h0);
    float r1 = f1 - __bfloat162float(h1);
    hi = pack_bf2(h0, h1);
    lo = pack_bf2(__float2bfloat16(r0), __float2bfloat16(r1));
}

// ---------------------------------------------------------------------------
// Split fp32 -> bf16 hi + bf16 lo (Markidis split). n % 4 == 0.
// ---------------------------------------------------------------------------
__global__ __launch_bounds__(256) void split_f32(
    const float* __restrict__ s, __nv_bfloat16* __restrict__ h,
    __nv_bfloat16* __restrict__ l, int n)
{
    int i = (blockIdx.x * 256 + threadIdx.x) * 4;
    if (i >= n) return;
    float4 v = *(const float4*)(s + i);
    uint32_t h01, l01, h23, l23;
    split2(v.x, v.y, h01, l01);
    split2(v.z, v.w, h23, l23);
    *(uint32_t*)(h + i)     = h01;  *(uint32_t*)(h + i + 2) = h23;
    *(uint32_t*)(l + i)     = l01;  *(uint32_t*)(l + i + 2) = l23;
}

// ---------------------------------------------------------------------------
// Tensor-core GEMM via mma.sync (bf16 3-way split, fp32 accum):
//   C[M,N] = (Ah+Al)[M,K] @ (Bh+Bl)[N,K]^T + bias[N]
// 128x256 CTA tile, BK=64, 512 threads / 16 warps (2x8), warp tile 64x32.
// 4 warps per SMSP for latency hiding. 2-stage cp.async pipeline.
// smem/stage: Ah,Al 16KB + Bh,Bl 32KB = 96KB; 2 stages = 192KB.
// ---------------------------------------------------------------------------
#define STAGE_BYTES 98304
#define A_BYTES     16384
#define B_BYTES     32768
#define OFF_AH 0
#define OFF_AL 16384
#define OFF_BH 32768
#define OFF_BL 65536

template<bool SPLIT_OUT>
__global__ __launch_bounds__(512, 1) void gemm_mma_split(
    const __nv_bfloat16* __restrict__ Ah, const __nv_bfloat16* __restrict__ Al,
    const __nv_bfloat16* __restrict__ Bh, const __nv_bfloat16* __restrict__ Bl,
    const float* __restrict__ bias, float* __restrict__ C,
    __nv_bfloat16* __restrict__ Ch, __nv_bfloat16* __restrict__ Cl, int N)
{
    extern __shared__ char smem[];
    const uint32_t sb = smem_to_u32(smem);
    const int tid  = threadIdx.x;
    const int lane = tid & 31;
    const int wid  = tid >> 5;
    const int wm   = wid >> 3;     // 0..1: 64-row slab
    const int wn   = wid & 7;      // 0..7: 32-col slab
    const int m0 = blockIdx.y * 128;
    const int n0 = blockIdx.x * 256;

    const __nv_bfloat16* const gA[2] = {
        Ah + (size_t)m0 * KDIM, Al + (size_t)m0 * KDIM };
    const __nv_bfloat16* const gB[2] = {
        Bh + (size_t)n0 * KDIM, Bl + (size_t)n0 * KDIM };

    float c[4][4][4];
    #pragma unroll
    for (int mt = 0; mt < 4; mt++)
        #pragma unroll
        for (int nt = 0; nt < 4; nt++)
            #pragma unroll
            for (int j = 0; j < 4; j++) c[mt][nt][j] = 0.f;

    // stage loader: A mats 128x64 bf16 (1024 16B units), B mats 256x64 (2048)
    auto issue = [&](int kc, int stage) {
        const uint32_t ss = sb + stage * STAGE_BYTES;
        #pragma unroll
        for (int t = 0; t < 2; t++) {
            const __nv_bfloat16* src = gA[t] + kc * 64;
            #pragma unroll
            for (int i = 0; i < 2; i++) {
                int u = i * 512 + tid, row = u >> 3, ch = u & 7;
                CP_ASYNC16(ss + OFF_AH + t * A_BYTES + row * 128 +
                           ((ch ^ (row & 7)) << 4),
                           src + (size_t)row * KDIM + ch * 8);
            }
        }
        #pragma unroll
        for (int t = 0; t < 2; t++) {
            const __nv_bfloat16* src = gB[t] + kc * 64;
            #pragma unroll
            for (int i = 0; i < 4; i++) {
                int u = i * 512 + tid, row = u >> 3, ch = u & 7;
                CP_ASYNC16(ss + OFF_BH + t * B_BYTES + row * 128 +
                           ((ch ^ (row & 7)) << 4),
                           src + (size_t)row * KDIM + ch * 8);
            }
        }
        CP_COMMIT();
    };

    auto compute = [&](int stage) {
        const uint32_t ss = sb + stage * STAGE_BYTES;
        #pragma unroll
        for (int ks = 0; ks < 4; ks++) {
            // A fragments: 4 m-tiles (16 rows), hi + lo
            uint32_t a_[4][4], al_[4][4];
            #pragma unroll
            for (int mt = 0; mt < 4; mt++) {
                int row = wm * 64 + mt * 16 + (lane & 15);
                int ch  = ks * 2 + (lane >> 4);
                uint32_t ad = ss + OFF_AH + row * 128 + ((ch ^ (row & 7)) << 4);
                LDSM_X4(a_[mt], ad);
                LDSM_X4(al_[mt], ad + A_BYTES);
            }
            // B fragments: 2 pairs of n-tiles via X4 (16 B-rows each), hi+lo
            uint32_t b_[2][4], bl_[2][4];
            #pragma unroll
            for (int p = 0; p < 2; p++) {
                int row = wn * 32 + p * 16 + ((lane >> 4) & 1) * 8 + (lane & 7);
                int ch  = ks * 2 + ((lane >> 3) & 1);
                uint32_t bd = ss + OFF_BH + row * 128 + ((ch ^ (row & 7)) << 4);
                LDSM_X4(b_[p], bd);
                LDSM_X4(bl_[p], bd + B_BYTES);
            }
            #pragma unroll
            for (int mt = 0; mt < 4; mt++)
                #pragma unroll
                for (int p = 0; p < 2; p++) {
                    MMA16816(c[mt][2*p],   a_[mt],  b_[p]);
                    MMA16816(c[mt][2*p],   a_[mt],  bl_[p]);
                    MMA16816(c[mt][2*p],   al_[mt], b_[p]);
                    MMA16816(c[mt][2*p+1], a_[mt],  b_[p] + 2);
                    MMA16816(c[mt][2*p+1], a_[mt],  bl_[p] + 2);
                    MMA16816(c[mt][2*p+1], al_[mt], b_[p] + 2);
                }
        }
    };

    const int nchunks = KDIM / 64;   // 16
    issue(0, 0);
    for (int kc = 0; kc < nchunks; kc++) {
        if (kc + 1 < nchunks) { issue(kc + 1, (kc + 1) & 1); CP_WAIT1(); }
        else                  { CP_WAIT0(); }
        __syncthreads();          // stage kc visible to all warps
        compute(kc & 1);
        __syncthreads();          // all warps done before stage reuse
    }

    #pragma unroll
    for (int mt = 0; mt < 4; mt++) {
        const int r = m0 + wm * 64 + mt * 16 + (lane >> 2);
        #pragma unroll
        for (int nt = 0; nt < 4; nt++) {
            const int cc = n0 + wn * 32 + nt * 8 + (lane & 3) * 2;
            float2 bi = *(const float2*)(bias + cc);
            float v0 = c[mt][nt][0] + bi.x, v1 = c[mt][nt][1] + bi.y;
            float v2 = c[mt][nt][2] + bi.x, v3 = c[mt][nt][3] + bi.y;
            if (!SPLIT_OUT) {
                *(float2*)(C + (size_t)r * N + cc)       = make_float2(v0, v1);
                *(float2*)(C + (size_t)(r + 8) * N + cc) = make_float2(v2, v3);
            } else {
                uint32_t hi, lo;
                split2(v0, v1, hi, lo);
                *(uint32_t*)(Ch + (size_t)r * N + cc) = hi;
                *(uint32_t*)(Cl + (size_t)r * N + cc) = lo;
                split2(v2, v3, hi, lo);
                *(uint32_t*)(Ch + (size_t)(r + 8) * N + cc) = hi;
                *(uint32_t*)(Cl + (size_t)(r + 8) * N + cc) = lo;
            }
        }
    }
}

// ---------------------------------------------------------------------------
// Tensor-core flash attention, causal, bf16 hi/lo split, fp32 accum.
// CTA: 256 query rows of one (b,h), 512 threads / 16 warps (16 rows each),
// 64-key tiles, 3-stage cp.async KV. Q fragments reloaded from smem per
// k16-step (saves registers; 512-thread CTAs cap at 128 regs/thread).
// ---------------------------------------------------------------------------
#define QT 256
#define KT 64
#define AQH 0
#define AQL 32768
#define AKV0 65536
#define AKV_STRIDE 32768
#define AKH 0
#define AKL 8192
#define AVH 16384
#define AVL 24576
#define ASMEM (65536 + 3 * 32768)   // 160 KB

__global__ __launch_bounds__(512, 1) void flash_attn_mma(
    const __nv_bfloat16* __restrict__ qkvh,
    const __nv_bfloat16* __restrict__ qkvl,
    __nv_bfloat16* __restrict__ ah, __nv_bfloat16* __restrict__ al)
{
    extern __shared__ char smem[];
    const uint32_t sb = smem_to_u32(smem);
    const int tid  = threadIdx.x;
    const int lane = tid & 31;
    const int w    = tid >> 5;     // 0..15
    const int qb   = (int)gridDim.x - 1 - (int)blockIdx.x;  // heavy-first
    const int bh   = blockIdx.y;
    const int b    = bh >> 4;
    const int h    = bh & 15;
    const int q0   = qb * QT;

    const size_t rowbase = (size_t)b * TT;
    const __nv_bfloat16* qh_g = qkvh + rowbase * QKVD + h * 192;
    const __nv_bfloat16* ql_g = qkvl + rowbase * QKVD + h * 192;

    // Q tiles (Qh, Ql): 256 rows x 64 bf16 = 2048 16B units each
    #pragma unroll
    for (int m = 0; m < 2; m++) {
        const __nv_bfloat16* src = m ? ql_g : qh_g;
        uint32_t dst = sb + (m ? AQL : AQH);
        #pragma unroll
        for (int i = 0; i < 4; i++) {
            int u = i * 512 + tid, row = u >> 3, ch = u & 7;
            CP_ASYNC16(dst + row * 128 + ((ch ^ (row & 7)) << 4),
                       src + (size_t)(q0 + row) * QKVD + ch * 8);
        }
    }

    auto load_kv = [&](int kb, int stage) {
        const int k0 = kb * KT;
        const uint32_t sv = sb + AKV0 + stage * AKV_STRIDE;
        const __nv_bfloat16* const srcs[4] = {
            qh_g + 64, ql_g + 64, qh_g + 128, ql_g + 128 };
        #pragma unroll
        for (int m = 0; m < 4; m++) {   // each matrix: 64 rows x 8 units = 512
            int row = tid >> 3, ch = tid & 7;
            CP_ASYNC16(sv + m * 8192 + row * 128 + ((ch ^ (row & 7)) << 4),
                       srcs[m] + (size_t)(k0 + row) * QKVD + ch * 8);
        }
        CP_COMMIT();
    };

    const int nkb = qb * 4 + 4;
    load_kv(0, 0);                 // group 0: Q + kv0
    load_kv(1, 1);                 // group 1: kv1 (nkb >= 4 always)
    CP_WAIT1();
    __syncthreads();

    float accO[8][4];
    #pragma unroll
    for (int nt = 0; nt < 8; nt++)
        #pragma unroll
        for (int j = 0; j < 4; j++) accO[nt][j] = 0.f;
    float m0 = -1e30f, m1 = -1e30f, l0 = 0.f, l1 = 0.f;

    const int r0 = q0 + w * 16 + (lane >> 2);   // this thread's row (and r0+8)
    const float scale = 0.125f * 1.4426950408889634f;   // base-2 softmax

    for (int kb = 0; kb < nkb; kb++) {
        if (kb + 2 < nkb) load_kv(kb + 2, (kb + 2) % 3);
        const uint32_t sv = sb + AKV0 + (kb % 3) * AKV_STRIDE;
        const int k0 = kb * KT;

        // ---- S = Qh*Kh + Qh*Kl + Ql*Kh  (16 x 64 per warp) ----
        float s[8][4];
        #pragma unroll
        for (int nt = 0; nt < 8; nt++)
            #pragma unroll
            for (int j = 0; j < 4; j++) s[nt][j] = 0.f;

        #pragma unroll
        for (int ks = 0; ks < 4; ks++) {
            // Q fragments for this k16-step (reloaded from smem)
            uint32_t qh4[4], ql4[4];
            {
                int row = w * 16 + (lane & 15);
                int ch  = ks * 2 + (lane >> 4);
                uint32_t off = row * 128 + ((ch ^ (row & 7)) << 4);
                LDSM_X4(qh4, sb + AQH + off);
                LDSM_X4(ql4, sb + AQL + off);
            }
            #pragma unroll
            for (int nt2 = 0; nt2 < 4; nt2++) {
                int row = nt2 * 16 + ((lane >> 4) & 1) * 8 + (lane & 7);
                int ch  = ks * 2 + ((lane >> 3) & 1);
                uint32_t off = row * 128 + ((ch ^ (row & 7)) << 4);
                uint32_t kh4[4], kl4[4];
                LDSM_X4(kh4, sv + AKH + off);
                LDSM_X4(kl4, sv + AKL + off);
                MMA16816(s[2 * nt2],     qh4, kh4);
                MMA16816(s[2 * nt2],     qh4, kl4);
                MMA16816(s[2 * nt2],     ql4, kh4);
                MMA16816(s[2 * nt2 + 1], qh4, kh4 + 2);
                MMA16816(s[2 * nt2 + 1], qh4, kl4 + 2);
                MMA16816(s[2 * nt2 + 1], ql4, kh4 + 2);
            }
        }

        // ---- scale (base-2) + causal mask ----
        const bool full = (k0 + KT - 1 <= q0 + w * 16);
        #pragma unroll
        for (int nt = 0; nt < 8; nt++) {
            int col = k0 + nt * 8 + (lane & 3) * 2;
            if (full) {
                s[nt][0] *= scale; s[nt][1] *= scale;
                s[nt][2] *= scale; s[nt][3] *= scale;
            } else {
                s[nt][0] = (col     <= r0)     ? s[nt][0] * scale : -1e30f;
                s[nt][1] = (col + 1 <= r0)     ? s[nt][1] * scale : -1e30f;
                s[nt][2] = (col     <= r0 + 8) ? s[nt][2] * scale : -1e30f;
                s[nt][3] = (col + 1 <= r0 + 8) ? s[nt][3] * scale : -1e30f;
            }
        }

        // ---- online softmax, base 2 (rows r0, r0+8; quad reductions) ----
        float mx0 = -1e30f, mx1 = -1e30f;
        #pragma unroll
        for (int nt = 0; nt < 8; nt++) {
            mx0 = fmaxf(mx0, fmaxf(s[nt][0], s[nt][1]));
            mx1 = fmaxf(mx1, fmaxf(s[nt][2], s[nt][3]));
        }
        mx0 = fmaxf(mx0, __shfl_xor_sync(0xffffffffu, mx0, 1));
        mx0 = fmaxf(mx0, __shfl_xor_sync(0xffffffffu, mx0, 2));
        mx1 = fmaxf(mx1, __shfl_xor_sync(0xffffffffu, mx1, 1));
        mx1 = fmaxf(mx1, __shfl_xor_sync(0xffffffffu, mx1, 2));
        const float mn0 = fmaxf(m0, mx0), mn1 = fmaxf(m1, mx1);
        const float a0 = ex2f(m0 - mn0), a1 = ex2f(m1 - mn1);
        m0 = mn0; m1 = mn1;
        float su0 = 0.f, su1 = 0.f;
        #pragma unroll
        for (int nt = 0; nt < 8; nt++) {
            s[nt][0] = ex2f(s[nt][0] - m0);
            s[nt][1] = ex2f(s[nt][1] - m0);
            s[nt][2] = ex2f(s[nt][2] - m1);
            s[nt][3] = ex2f(s[nt][3] - m1);
            su0 += s[nt][0] + s[nt][1];
            su1 += s[nt][2] + s[nt][3];
        }
        su0 += __shfl_xor_sync(0xffffffffu, su0, 1);
        su0 += __shfl_xor_sync(0xffffffffu, su0, 2);
        su1 += __shfl_xor_sync(0xffffffffu, su1, 1);
        su1 += __shfl_xor_sync(0xffffffffu, su1, 2);
        l0 = l0 * a0 + su0;
        l1 = l1 * a1 + su1;
        #pragma unroll
        for (int nt = 0; nt < 8; nt++) {
            accO[nt][0] *= a0; accO[nt][1] *= a0;
            accO[nt][2] *= a1; accO[nt][3] *= a1;
        }

        // ---- pack P into A-fragments (hi + residual lo), register-only ----
        uint32_t ph[4][4], pl[4][4];
        #pragma unroll
        for (int t = 0; t < 4; t++) {
            split2(s[2*t][0],   s[2*t][1],   ph[t][0], pl[t][0]);
            split2(s[2*t][2],   s[2*t][3],   ph[t][1], pl[t][1]);
            split2(s[2*t+1][0], s[2*t+1][1], ph[t][2], pl[t][2]);
            split2(s[2*t+1][2], s[2*t+1][3], ph[t][3], pl[t][3]);
        }

        // ---- O += Ph*Vh + Ph*Vl + Pl*Vh  (V via ldmatrix.trans) ----
        #pragma unroll
        for (int ks = 0; ks < 4; ks++) {
            #pragma unroll
            for (int nt2 = 0; nt2 < 4; nt2++) {
                int row = ks * 16 + ((lane >> 3) & 1) * 8 + (lane & 7);
                int ch  = nt2 * 2 + ((lane >> 4) & 1);
                uint32_t off = row * 128 + ((ch ^ (row & 7)) << 4);
                uint32_t vh4[4], vl4[4];
                LDSM_X4_T(vh4, sv + AVH + off);
                LDSM_X4_T(vl4, sv + AVL + off);
                MMA16816(accO[2 * nt2],     ph[ks], vh4);
                MMA16816(accO[2 * nt2],     ph[ks], vl4);
                MMA16816(accO[2 * nt2],     pl[ks], vh4);
                MMA16816(accO[2 * nt2 + 1], ph[ks], vh4 + 2);
                MMA16816(accO[2 * nt2 + 1], ph[ks], vl4 + 2);
                MMA16816(accO[2 * nt2 + 1], pl[ks], vh4 + 2);
            }
        }

        if (kb + 1 < nkb) {
            if (kb + 2 < nkb) CP_WAIT1(); else CP_WAIT0();
            __syncthreads();   // kv(kb+1) ready; all warps done with kb%3
        }
    }

    // ---- epilogue: normalize, split to bf16 hi/lo, write [row][h*64+d] ----
    const float i0 = 1.f / l0, i1 = 1.f / l1;
    #pragma unroll
    for (int nt = 0; nt < 8; nt++) {
        const int col = h * HD + nt * 8 + (lane & 3) * 2;
        uint32_t hi, lo;
        split2(accO[nt][0] * i0, accO[nt][1] * i0, hi, lo);
        size_t o0 = (rowbase + r0) * DD + col;
        *(uint32_t*)(ah + o0) = hi;
        *(uint32_t*)(al + o0) = lo;
        split2(accO[nt][2] * i1, accO[nt][3] * i1, hi, lo);
        size_t o1 = (rowbase + r0 + 8) * DD + col;
        *(uint32_t*)(ah + o1) = hi;
        *(uint32_t*)(al + o1) = lo;
    }
}

// ---------------------------------------------------------------------------
// Launch pipeline
// ---------------------------------------------------------------------------
extern "C" void kernel_launch(void* const* d_in, const int* in_sizes, int n_in,
                              void* d_out, int out_size)
{
    const float* x    = (const float*)d_in[0];  // [B,T,D]
    const float* Wqkv = (const float*)d_in[1];  // [3D,D]
    const float* bqkv = (const float*)d_in[2];  // [3D]
    const float* Wout = (const float*)d_in[3];  // [D,D]
    const float* bout = (const float*)d_in[4];  // [D]
    float* out = (float*)d_out;                 // [B,T,D]

    __nv_bfloat16 *xh, *xl, *wqh, *wql, *woh, *wol, *qvh, *qvl, *ah, *al;
    cudaGetSymbolAddress((void**)&xh,  g_xh);
    cudaGetSymbolAddress((void**)&xl,  g_xl);
    cudaGetSymbolAddress((void**)&wqh, g_wqh);
    cudaGetSymbolAddress((void**)&wql, g_wql);
    cudaGetSymbolAddress((void**)&woh, g_woh);
    cudaGetSymbolAddress((void**)&wol, g_wol);
    cudaGetSymbolAddress((void**)&qvh, g_qkvh);
    cudaGetSymbolAddress((void**)&qvl, g_qkvl);
    cudaGetSymbolAddress((void**)&ah,  g_ah);
    cudaGetSymbolAddress((void**)&al,  g_al);

    cudaFuncSetAttribute(gemm_mma_split<true>,
                         cudaFuncAttributeMaxDynamicSharedMemorySize,
                         2 * STAGE_BYTES);
    cudaFuncSetAttribute(gemm_mma_split<false>,
                         cudaFuncAttributeMaxDynamicSharedMemorySize,
                         2 * STAGE_BYTES);
    cudaFuncSetAttribute(flash_attn_mma,
                         cudaFuncAttributeMaxDynamicSharedMemorySize, ASMEM);

    // 1) split inputs and weights to bf16 hi/lo
    split_f32<<<(MM * DD) / 1024, 256>>>(x, xh, xl, MM * DD);
    split_f32<<<(QKVD * DD) / 1024, 256>>>(Wqkv, wqh, wql, QKVD * DD);
    split_f32<<<(DD * DD) / 1024, 256>>>(Wout, woh, wol, DD * DD);

    // 2) QKV projection -> split bf16 output directly (CTA 128x256, 512 thr)
    gemm_mma_split<true><<<dim3(QKVD / 256, MM / 128), 512, 2 * STAGE_BYTES>>>(
        xh, xl, wqh, wql, bqkv, nullptr, qvh, qvl, QKVD);

    // 3) causal flash attention on tensor cores -> split bf16 output
    flash_attn_mma<<<dim3(TT / QT, BB * HH), 512, ASMEM>>>(qvh, qvl, ah, al);

    // 4) output projection -> fp32 final output (CTA 128x256, 512 thr)
    gemm_mma_split<false><<<dim3(DD / 256, MM / 128), 512, 2 * STAGE_BYTES>>>(
        ah, al, woh, wol, bout, out, nullptr, nullptr, DD);
}